// round 11
// baseline (speedup 1.0000x reference)
#include <cuda_runtime.h>
#include <cuda_bf16.h>
#include <math.h>
#include <stdint.h>

// Problem constants
#define NB    2
#define NL    2048
#define NH    16
#define ND    64
#define NDIM  1024
#define NC    8
#define NPC   256
#define NG    16
#define NBC   (NB*NC)

// Scratch (device globals; no allocation allowed)
__device__ float g_Mq [NBC*NPC*NG*16];
__device__ float g_Mkv[NBC*NPC*NG*16];
__device__ float g_Mo [NBC*NPC*NG*16];
__device__ float g_P  [NBC*16];
__device__ float g_Pi [NBC*16];

// bf16 hi/lo split buffers (GEMM operands): per 32-float chunk -> [32 hi | 32 lo]
__device__ __align__(128) __nv_bfloat16 g_xs [4096*2048];   // x split
__device__ __align__(128) __nv_bfloat16 g_wqs[3072*2048];   // w_qkv split
__device__ __align__(128) __nv_bfloat16 g_wps[1024*2048];   // w_proj split
__device__ __align__(128) __nv_bfloat16 g_ys [4096*2048];   // attention out split

// attention operands: [bh][token][hi d0..63 | lo d0..63] bf16 (256B rows)
__device__ __align__(128) __nv_bfloat16 g_qs [32*2048*128];
__device__ __align__(128) __nv_bfloat16 g_ks [32*2048*128];
__device__ __align__(128) __nv_bfloat16 g_vs [32*2048*128];

// ---------------------------------------------------------------------------
// PTX helpers (sm_103-safe: mma.sync / ldmatrix / cp.async only)
// ---------------------------------------------------------------------------
__device__ __forceinline__ uint32_t smem_u32(const void* p) {
    uint32_t a;
    asm("{ .reg .u64 t; cvta.to.shared.u64 t, %1; cvt.u32.u64 %0, t; }" : "=r"(a) : "l"(p));
    return a;
}
__device__ __forceinline__ void cpa16(uint32_t sdst, const void* gsrc) {
    asm volatile("cp.async.cg.shared.global [%0], [%1], 16;" :: "r"(sdst), "l"(gsrc) : "memory");
}
#define CP_COMMIT() asm volatile("cp.async.commit_group;" ::: "memory")
#define CP_WAIT(n)  asm volatile("cp.async.wait_group %0;" :: "n"(n) : "memory")

__device__ __forceinline__ void ldsm_x4(uint32_t addr, uint32_t* r) {
    asm volatile("ldmatrix.sync.aligned.m8n8.x4.shared.b16 {%0,%1,%2,%3}, [%4];"
        : "=r"(r[0]), "=r"(r[1]), "=r"(r[2]), "=r"(r[3]) : "r"(addr));
}
__device__ __forceinline__ void ldsm_x4_t(uint32_t addr, uint32_t* r) {
    asm volatile("ldmatrix.sync.aligned.m8n8.x4.trans.shared.b16 {%0,%1,%2,%3}, [%4];"
        : "=r"(r[0]), "=r"(r[1]), "=r"(r[2]), "=r"(r[3]) : "r"(addr));
}
__device__ __forceinline__ void mma16816(float* c, const uint32_t* a, uint32_t b0, uint32_t b1) {
    asm volatile("mma.sync.aligned.m16n8k16.row.col.f32.bf16.bf16.f32 "
        "{%0,%1,%2,%3}, {%4,%5,%6,%7}, {%8,%9}, {%0,%1,%2,%3};"
        : "+f"(c[0]), "+f"(c[1]), "+f"(c[2]), "+f"(c[3])
        : "r"(a[0]), "r"(a[1]), "r"(a[2]), "r"(a[3]), "r"(b0), "r"(b1));
}
// swizzled smem address: 256B-pitch rows, 16B segs, seg ^= row&7
__device__ __forceinline__ uint32_t asw(uint32_t base, int row, int seg) {
    return base + row * 256 + ((seg ^ (row & 7)) << 4);
}
// 128B-pitch version
__device__ __forceinline__ uint32_t sw_addr(uint32_t base, int row, int seg) {
    return base + row * 128 + ((seg ^ (row & 7)) << 4);
}

// ---------------------------------------------------------------------------
// Kernel 1: per-camera P = K4 @ viewmat and analytic P^{-1}
// ---------------------------------------------------------------------------
__global__ void cam_kernel(const float* __restrict__ vm, const float* __restrict__ Kin) {
    int t = threadIdx.x;
    if (t >= NBC) return;
    const float* V = vm + t * 16;
    const float* K = Kin + t * 9;
    float P[16];
#pragma unroll
    for (int i = 0; i < 3; i++)
#pragma unroll
        for (int j = 0; j < 4; j++)
            P[i*4+j] = K[i*3+0]*V[0+j] + K[i*3+1]*V[4+j] + K[i*3+2]*V[8+j];
    P[12] = V[12]; P[13] = V[13]; P[14] = V[14]; P[15] = V[15];

    float Vi[16];
#pragma unroll
    for (int i = 0; i < 3; i++) {
#pragma unroll
        for (int j = 0; j < 3; j++) Vi[i*4+j] = V[j*4+i];
        Vi[i*4+3] = -(V[0*4+i]*V[3] + V[1*4+i]*V[7] + V[2*4+i]*V[11]);
    }
    Vi[12] = 0.f; Vi[13] = 0.f; Vi[14] = 0.f; Vi[15] = 1.f;

    float f = K[0], cx = K[2], cy = K[5];
    float invf = 1.0f / f;
    float Pi[16];
#pragma unroll
    for (int i = 0; i < 4; i++) {
        float c0 = Vi[i*4+0] * invf;
        float c1 = Vi[i*4+1] * invf;
        Pi[i*4+0] = c0;
        Pi[i*4+1] = c1;
        Pi[i*4+2] = Vi[i*4+2] - cx*c0 - cy*c1;
        Pi[i*4+3] = Vi[i*4+3];
    }
#pragma unroll
    for (int i = 0; i < 16; i++) { g_P[t*16+i] = P[i]; g_Pi[t*16+i] = Pi[i]; }
}

// ---------------------------------------------------------------------------
// Kernel 2: per-(b,c,p,g) transforms Mq, Mkv, Mo
// ---------------------------------------------------------------------------
__global__ void m_kernel() {
    int i = blockIdx.x * blockDim.x + threadIdx.x;
    int g  = i & 15;
    int p  = (i >> 4) & 255;
    int bc = i >> 12;
    const float* P  = g_P  + bc * 16;
    const float* Pi = g_Pi + bc * 16;

    float u = ((p & 15) + 0.5f) * 16.0f;
    float v = ((p >> 4) + 0.5f) * 16.0f;
    float fr = powf(10000.0f, -(float)g / 16.0f);
    float sa, ca, sb, cb;
    sincosf(u * fr, &sa, &ca);
    sincosf(v * fr, &sb, &cb);

    float* mq  = g_Mq  + i * 16;
    float* mkv = g_Mkv + i * 16;
    float* mo  = g_Mo  + i * 16;
#pragma unroll
    for (int r = 0; r < 4; r++) {
        float p0 = Pi[0*4+r], p1 = Pi[1*4+r], p2 = Pi[2*4+r], p3 = Pi[3*4+r];
        mq[r*4+0] =  p0*ca + p1*sa;
        mq[r*4+1] = -p0*sa + p1*ca;
        mq[r*4+2] =  p2*cb + p3*sb;
        mq[r*4+3] = -p2*sb + p3*cb;
        float q0 = P[r*4+0], q1 = P[r*4+1], q2 = P[r*4+2], q3 = P[r*4+3];
        mkv[r*4+0] =  q0*ca + q1*sa;
        mkv[r*4+1] = -q0*sa + q1*ca;
        mkv[r*4+2] =  q2*cb + q3*sb;
        mkv[r*4+3] = -q2*sb + q3*cb;
    }
#pragma unroll
    for (int k = 0; k < 4; k++) {
        float p0 = Pi[0*4+k], p1 = Pi[4+k], p2 = Pi[8+k], p3 = Pi[12+k];
        mo[0*4+k] =  ca*p0 + sa*p1;
        mo[1*4+k] = -sa*p0 + ca*p1;
        mo[2*4+k] =  cb*p2 + sb*p3;
        mo[3*4+k] = -sb*p2 + cb*p3;
    }
}

// ---------------------------------------------------------------------------
// bf16 hi/lo split for all three GEMM inputs, one launch.
// ---------------------------------------------------------------------------
__global__ void __launch_bounds__(256) split3_kernel(const float* __restrict__ x,
                                                     const float* __restrict__ wq,
                                                     const float* __restrict__ wp) {
    int c = blockIdx.x * 256 + threadIdx.x;
    const float* src; __nv_bfloat16* dst; int cc;
    if (c < 131072)      { src = x;  dst = g_xs;  cc = c; }
    else if (c < 229376) { src = wq; dst = g_wqs; cc = c - 131072; }
    else                 { src = wp; dst = g_wps; cc = c - 229376; }
    const float4* s = (const float4*)src + (size_t)cc * 8;
    __nv_bfloat162 H[16], L[16];
#pragma unroll
    for (int i = 0; i < 8; i++) {
        float4 f = s[i];
        float vv[4] = {f.x, f.y, f.z, f.w};
#pragma unroll
        for (int j = 0; j < 2; j++) {
            float a = vv[2*j], b = vv[2*j+1];
            __nv_bfloat16 ha = __float2bfloat16_rn(a);
            __nv_bfloat16 hb = __float2bfloat16_rn(b);
            __nv_bfloat16 la = __float2bfloat16_rn(a - __bfloat162float(ha));
            __nv_bfloat16 lb = __float2bfloat16_rn(b - __bfloat162float(hb));
            H[i*2+j] = __halves2bfloat162(ha, hb);
            L[i*2+j] = __halves2bfloat162(la, lb);
        }
    }
    uint4* d = (uint4*)(dst + (size_t)cc * 64);
    const uint4* hv = (const uint4*)H;
    const uint4* lv = (const uint4*)L;
#pragma unroll
    for (int i = 0; i < 4; i++) d[i] = hv[i];
#pragma unroll
    for (int i = 0; i < 4; i++) d[4+i] = lv[i];
}

// ---------------------------------------------------------------------------
// mma.sync split-bf16 GEMM, GS=3, 2 CTAs/SM, ONE sync per stage, load-first.
// MODE 0: qkv — fused Mq/Mkv transform epilogue -> split bf16 g_qs/g_ks/g_vs
// MODE 1: proj — plain fp32 epilogue to Cout
// ---------------------------------------------------------------------------
#define GS        3
#define GSTAGE_B  32768
#define GSM_TOTAL (GS*GSTAGE_B)   // 98304

__device__ __forceinline__ void g_load_stage(uint32_t sA, uint32_t sB,
        const char* Ab, const char* Bb, int m0, int n0, int kc, int tid) {
#pragma unroll
    for (int it = 0; it < 4; it++) {
        int u = tid + it * 256;
        int r = u >> 3, s = u & 7;
        cpa16(sw_addr(sA, r, s), Ab + ((size_t)(m0 + r) * 32 + kc) * 128 + s * 16);
    }
#pragma unroll
    for (int it = 0; it < 4; it++) {
        int u = tid + it * 256;
        int r = u >> 3, s = u & 7;
        cpa16(sw_addr(sB, r, s), Bb + ((size_t)(n0 + r) * 32 + kc) * 128 + s * 16);
    }
}

template <int MODE>
__global__ void __launch_bounds__(256, 2) gemm_mma(const __nv_bfloat16* __restrict__ Abf,
                                                   const __nv_bfloat16* __restrict__ Bbf,
                                                   float* __restrict__ Cout) {
    extern __shared__ char smem[];
    uint32_t sb = smem_u32(smem);
    int tid = threadIdx.x, wid = tid >> 5, lane = tid & 31;
    int m0 = blockIdx.y * 128, n0 = blockIdx.x * 128;
    const char* Ab = (const char*)Abf;
    const char* Bb = (const char*)Bbf;

    int wm = (wid & 3) * 32;
    int wn = (wid >> 2) * 64;
    int lrow = lane & 7;
    int lm8  = (lane >> 3) & 1;
    int lk   = lane >> 4;

    float acc[2][8][4];
#pragma unroll
    for (int t = 0; t < 2; t++)
#pragma unroll
        for (int g = 0; g < 8; g++)
#pragma unroll
            for (int r = 0; r < 4; r++) acc[t][g][r] = 0.f;

    // prologue: prefetch chunks 0..GS-2
#pragma unroll
    for (int s = 0; s < GS - 1; s++) {
        uint32_t sA = sb + s * GSTAGE_B;
        g_load_stage(sA, sA + 16384, Ab, Bb, m0, n0, s, tid);
        CP_COMMIT();
    }

    const int stepA[6] = {0, 2, 0, 2, 4, 6};
    const int stepB[6] = {0, 2, 4, 6, 0, 2};

    int sload = GS - 1;   // slot receiving chunk i+GS-1
    int scomp = 0;        // slot holding chunk i
    for (int i = 0; i < 32; i++) {
        CP_WAIT(GS - 2);        // FIFO retirement => chunk i resident
        __syncthreads();        // all warps done reading slot sload (iter i-1)
        if (i + GS - 1 < 32) {
            uint32_t dA = sb + sload * GSTAGE_B;
            g_load_stage(dA, dA + 16384, Ab, Bb, m0, n0, i + GS - 1, tid);
        }
        CP_COMMIT();
        uint32_t sA = sb + scomp * GSTAGE_B;
        uint32_t sB = sA + 16384;
#pragma unroll
        for (int st = 0; st < 6; st++) {
            int sa0 = stepA[st], sb0 = stepB[st];
            uint32_t a[2][4];
#pragma unroll
            for (int t = 0; t < 2; t++) {
                int row = wm + t * 16 + lm8 * 8 + lrow;
                ldsm_x4(sw_addr(sA, row, sa0 + lk), a[t]);
            }
            uint32_t b[4][4];
#pragma unroll
            for (int g = 0; g < 4; g++) {
                int row = wn + g * 16 + lm8 * 8 + lrow;
                ldsm_x4(sw_addr(sB, row, sb0 + lk), b[g]);
            }
#pragma unroll
            for (int t = 0; t < 2; t++)
#pragma unroll
                for (int g = 0; g < 4; g++) {
                    mma16816(acc[t][2*g],   a[t], b[g][0], b[g][2]);
                    mma16816(acc[t][2*g+1], a[t], b[g][1], b[g][3]);
                }
        }
        sload = (sload + 1 == GS) ? 0 : sload + 1;
        scomp = (scomp + 1 == GS) ? 0 : scomp + 1;
    }

    int mrow = (lane >> 2);
    int ncol = (lane & 3) * 2;

    if (MODE == 1) {
#pragma unroll
        for (int t = 0; t < 2; t++)
#pragma unroll
            for (int g = 0; g < 8; g++) {
                int n = n0 + wn + (g >> 1) * 16 + (g & 1) * 8 + ncol;
                int m = m0 + wm + t * 16 + mrow;
#pragma unroll
                for (int half = 0; half < 2; half++) {
                    int mm = m + half * 8;
                    *(float2*)(Cout + (size_t)mm * NDIM + n) =
                        make_float2(acc[t][g][half*2], acc[t][g][half*2+1]);
                }
            }
        return;
    }

    // MODE 0: fused transform epilogue. Stage fp32 tile in smem (pitch 132).
    CP_WAIT(0);
    __syncthreads();
    float* os = (float*)smem;
#pragma unroll
    for (int t = 0; t < 2; t++)
#pragma unroll
        for (int g = 0; g < 8; g++) {
            int nn = wn + (g >> 1) * 16 + (g & 1) * 8 + ncol;
#pragma unroll
            for (int half = 0; half < 2; half++) {
                int mmr = wm + t * 16 + mrow + half * 8;
                *(float2*)&os[mmr * 132 + nn] =
                    make_float2(acc[t][g][half*2], acc[t][g][half*2+1]);
            }
        }
    __syncthreads();

    int tt = n0 >> 10;   // 0=q, 1=k, 2=v
    const float* Mbase = (tt == 0) ? g_Mq : g_Mkv;
    __nv_bfloat16* obase = (tt == 0) ? g_qs : (tt == 1) ? g_ks : g_vs;
    float qscale = (tt == 0) ? 0.125f : 1.0f;
#pragma unroll
    for (int it2 = 0; it2 < 16; it2++) {
        int idx = tid + it2 * 256;
        int row = idx >> 5, gi = idx & 31;
        int m = m0 + row;
        int b = m >> 11, l = m & 2047;
        int n = n0 + gi * 4;
        int h = (n >> 6) & 15, g = (n & 63) >> 2;
        int c = l >> 8, p = l & 255;
        const float* M = Mbase + ((size_t)(((b << 3) + c) * NPC + p) * NG + g) * 16;
        float4 tv = *(float4*)&os[row * 132 + gi * 4];
        float y0 = (M[0]*tv.x  + M[1]*tv.y  + M[2]*tv.z  + M[3]*tv.w)  * qscale;
        float y1 = (M[4]*tv.x  + M[5]*tv.y  + M[6]*tv.z  + M[7]*tv.w)  * qscale;
        float y2 = (M[8]*tv.x  + M[9]*tv.y  + M[10]*tv.z + M[11]*tv.w) * qscale;
        float y3 = (M[12]*tv.x + M[13]*tv.y + M[14]*tv.z + M[15]*tv.w) * qscale;
        __nv_bfloat16 hi[4], lo[4];
        float vv[4] = {y0, y1, y2, y3};
#pragma unroll
        for (int j = 0; j < 4; j++) {
            hi[j] = __float2bfloat16_rn(vv[j]);
            lo[j] = __float2bfloat16_rn(vv[j] - __bfloat162float(hi[j]));
        }
        size_t tb = ((size_t)((b << 4) + h) * NL + l) * 128;
        *(uint2*)(obase + tb + g * 4)      = *(uint2*)hi;
        *(uint2*)(obase + tb + 64 + g * 4) = *(uint2*)lo;
    }
}

// ---------------------------------------------------------------------------
// Kernel 5: flash attention with split-bf16 mma.sync, 2 CTAs/SM (unchanged).
// ---------------------------------------------------------------------------
#define ATTN_SMEM 98304

__device__ __forceinline__ void attn_load_kv(uint32_t Kb, uint32_t Vb,
        const char* Ksrc, const char* Vsrc, int tid) {
#pragma unroll
    for (int it2 = 0; it2 < 4; it2++) {
        int u = tid + it2 * 256;
        int r = u >> 4, s = u & 15;
        cpa16(asw(Kb, r, s), Ksrc + (size_t)r * 256 + s * 16);
    }
#pragma unroll
    for (int it2 = 0; it2 < 4; it2++) {
        int u = tid + it2 * 256;
        int r = u >> 4, s = u & 15;
        cpa16(asw(Vb, r, s), Vsrc + (size_t)r * 256 + s * 16);
    }
}

__global__ void __launch_bounds__(256, 2) attn_mma() {
    extern __shared__ char smem[];
    uint32_t sb = smem_u32(smem);
    uint32_t Qs = sb;                       // 128 rows x 256B
    int bh = blockIdx.y;
    int b = bh >> 4, h = bh & 15;
    int q0 = blockIdx.x * 128;
    int tid = threadIdx.x, wid = tid >> 5, lane = tid & 31;

    const char* Qg = (const char*)g_qs + ((size_t)bh * NL + q0) * 256;
    const char* Kg = (const char*)g_ks + (size_t)bh * NL * 256;
    const char* Vg = (const char*)g_vs + (size_t)bh * NL * 256;

#pragma unroll
    for (int it2 = 0; it2 < 8; it2++) {
        int u = tid + it2 * 256;
        int r = u >> 4, s = u & 15;
        cpa16(asw(Qs, r, s), Qg + (size_t)r * 256 + s * 16);
    }
    attn_load_kv(sb + 32768, sb + 32768 + 16384, Kg, Vg, tid);
    CP_COMMIT();
    CP_WAIT(0);
    __syncthreads();

    int wq = wid * 16;
    int lrow8 = (lane & 7) + ((lane >> 3) & 1) * 8;
    int lseg  = lane >> 4;
    uint32_t qh[4][4];
#pragma unroll
    for (int kc = 0; kc < 4; kc++)
        ldsm_x4(asw(Qs, wq + lrow8, kc*2 + lseg), qh[kc]);

    float oacc[8][4];
#pragma unroll
    for (int n = 0; n < 8; n++)
#pragma unroll
        for (int r = 0; r < 4; r++) oacc[n][r] = 0.f;
    float mi0 = -1e30f, mi1 = -1e30f, li0 = 0.f, li1 = 0.f;

    for (int it = 0; it < 32; it++) {
        if (it + 1 < 32)
            attn_load_kv(sb + 32768 + ((it+1)&1)*32768, sb + 32768 + ((it+1)&1)*32768 + 16384,
                         Kg + (size_t)(it+1)*64*256, Vg + (size_t)(it+1)*64*256, tid);
        CP_COMMIT();
        uint32_t Kb = sb + 32768 + (it&1)*32768;
        uint32_t Vb = Kb + 16384;

        // S = Q K^T (3-term split; Q-lo frag reloaded from smem)
        float sacc[8][4];
#pragma unroll
        for (int n = 0; n < 8; n++)
#pragma unroll
            for (int r = 0; r < 4; r++) sacc[n][r] = 0.f;
#pragma unroll
        for (int kc = 0; kc < 4; kc++) {
            uint32_t ql[4];
            ldsm_x4(asw(Qs, wq + lrow8, 8 + kc*2 + lseg), ql);
#pragma unroll
            for (int np = 0; np < 4; np++) {
                uint32_t kh[4], kl[4];
                int krow = np*16 + lrow8;
                ldsm_x4(asw(Kb, krow, kc*2 + lseg), kh);
                ldsm_x4(asw(Kb, krow, 8 + kc*2 + lseg), kl);
                mma16816(sacc[2*np],   qh[kc], kh[0], kh[2]);
                mma16816(sacc[2*np+1], qh[kc], kh[1], kh[3]);
                mma16816(sacc[2*np],   qh[kc], kl[0], kl[2]);
                mma16816(sacc[2*np+1], qh[kc], kl[1], kl[3]);
                mma16816(sacc[2*np],   ql, kh[0], kh[2]);
                mma16816(sacc[2*np+1], ql, kh[1], kh[3]);
            }
        }

        // online softmax (rows r = lane>>2 and r+8)
        float m0 = -1e30f, m1 = -1e30f;
#pragma unroll
        for (int n = 0; n < 8; n++) {
            m0 = fmaxf(m0, fmaxf(sacc[n][0], sacc[n][1]));
            m1 = fmaxf(m1, fmaxf(sacc[n][2], sacc[n][3]));
        }
        m0 = fmaxf(m0, __shfl_xor_sync(0xffffffffu, m0, 1));
        m0 = fmaxf(m0, __shfl_xor_sync(0xffffffffu, m0, 2));
        m1 = fmaxf(m1, __shfl_xor_sync(0xffffffffu, m1, 1));
        m1 = fmaxf(m1, __shfl_xor_sync(0xffffffffu, m1, 2));
        float nm0 = fmaxf(mi0, m0), nm1 = fmaxf(mi1, m1);
        float al0 = __expf(mi0 - nm0), al1 = __expf(mi1 - nm1);
        mi0 = nm0; mi1 = nm1;

        float rs0 = 0.f, rs1 = 0.f;
#pragma unroll
        for (int n = 0; n < 8; n++) {
            sacc[n][0] = __expf(sacc[n][0] - nm0);
            sacc[n][1] = __expf(sacc[n][1] - nm0);
            sacc[n][2] = __expf(sacc[n][2] - nm1);
            sacc[n][3] = __expf(sacc[n][3] - nm1);
            rs0 += sacc[n][0] + sacc[n][1];
            rs1 += sacc[n][2] + sacc[n][3];
        }
        rs0 += __shfl_xor_sync(0xffffffffu, rs0, 1);
        rs0 += __shfl_xor_sync(0xffffffffu, rs0, 2);
        rs1 += __shfl_xor_sync(0xffffffffu, rs1, 1);
        rs1 += __shfl_xor_sync(0xffffffffu, rs1, 2);
        li0 = li0 * al0 + rs0;
        li1 = li1 * al1 + rs1;
#pragma unroll
        for (int n = 0; n < 8; n++) {
            oacc[n][0] *= al0; oacc[n][1] *= al0;
            oacc[n][2] *= al1; oacc[n][3] *= al1;
        }

        // O += P V (3-term split); P converted per-kc from sacc
#pragma unroll
        for (int kc = 0; kc < 4; kc++) {
            uint32_t af[4], amf[4];
#pragma unroll
            for (int half = 0; half < 2; half++) {
                const float* s0 = sacc[2*kc + half];
                __nv_bfloat162 h01 = __floats2bfloat162_rn(s0[0], s0[1]);
                __nv_bfloat162 h23 = __floats2bfloat162_rn(s0[2], s0[3]);
                float2 f01 = __bfloat1622float2(h01);
                float2 f23 = __bfloat1622float2(h23);
                __nv_bfloat162 l01 = __floats2bfloat162_rn(s0[0] - f01.x, s0[1] - f01.y);
                __nv_bfloat162 l23 = __floats2bfloat162_rn(s0[2] - f23.x, s0[3] - f23.y);
                af[half*2]   = *(uint32_t*)&h01;
                af[half*2+1] = *(uint32_t*)&h23;
                amf[half*2]   = *(uint32_t*)&l01;
                amf[half*2+1] = *(uint32_t*)&l23;
            }
#pragma unroll
            for (int dp = 0; dp < 4; dp++) {
                uint32_t vh[4], vl[4];
                int vrow = kc*16 + lrow8;
                ldsm_x4_t(asw(Vb, vrow, dp*2 + lseg), vh);
                ldsm_x4_t(asw(Vb, vrow, 8 + dp*2 + lseg), vl);
                mma16816(oacc[2*dp],   af, vh[0], vh[1]);
                mma16816(oacc[2*dp+1], af, vh[2], vh[3]);
                mma16816(oacc[2*dp],   af, vl[0], vl[1]);
                mma16816(oacc[2*dp+1], af, vl[2], vl[3]);
                mma16816(oacc[2*dp],   amf, vh[0], vh[1]);
                mma16816(oacc[2*dp+1], amf, vh[2], vh[3]);
            }
        }
        if (it + 1 < 32) { CP_WAIT(0); __syncthreads(); }
    }

    // epilogue: normalized o -> smem, then Mo + split-store to g_ys
    __syncthreads();
    float* os = (float*)(smem + 32768);   // [128][65] f32
    float inv0 = 1.0f / li0, inv1 = 1.0f / li1;
    int r = wq + (lane >> 2);
    int cb = (lane & 3) * 2;
#pragma unroll
    for (int n = 0; n < 8; n++) {
        os[r*65 + n*8 + cb]         = oacc[n][0] * inv0;
        os[r*65 + n*8 + cb + 1]     = oacc[n][1] * inv0;
        os[(r+8)*65 + n*8 + cb]     = oacc[n][2] * inv1;
        os[(r+8)*65 + n*8 + cb + 1] = oacc[n][3] * inv1;
    }
    __syncthreads();

#pragma unroll
    for (int it2 = 0; it2 < 8; it2++) {
        int u = tid + it2 * 256;
        int qq = u >> 4, g = u & 15;
        int l = q0 + qq;
        int c = l >> 8, p = l & 255;
        const float* Mo = g_Mo + ((size_t)(((b << 3) + c) * NPC + p) * NG + g) * 16;
        float o0 = os[qq*65 + g*4 + 0];
        float o1 = os[qq*65 + g*4 + 1];
        float o2 = os[qq*65 + g*4 + 2];
        float o3 = os[qq*65 + g*4 + 3];
        float y0 = Mo[0]*o0  + Mo[1]*o1  + Mo[2]*o2  + Mo[3]*o3;
        float y1 = Mo[4]*o0  + Mo[5]*o1  + Mo[6]*o2  + Mo[7]*o3;
        float y2 = Mo[8]*o0  + Mo[9]*o1  + Mo[10]*o2 + Mo[11]*o3;
        float y3 = Mo[12]*o0 + Mo[13]*o1 + Mo[14]*o2 + Mo[15]*o3;
        __nv_bfloat16 hi[4], lo[4];
        float vv[4] = {y0, y1, y2, y3};
#pragma unroll
        for (int j = 0; j < 4; j++) {
            hi[j] = __float2bfloat16_rn(vv[j]);
            lo[j] = __float2bfloat16_rn(vv[j] - __bfloat162float(hi[j]));
        }
        int m = b * NL + l;
        int col = h * 64 + g * 4;
        int chunk = col >> 5, cof = col & 31;
        __nv_bfloat16* dst = g_ys + ((size_t)m * 32 + chunk) * 64 + cof;
        *(uint2*)dst        = *(uint2*)hi;
        *(uint2*)(dst + 32) = *(uint2*)lo;
    }
}

// ---------------------------------------------------------------------------
extern "C" void kernel_launch(void* const* d_in, const int* in_sizes, int n_in,
                              void* d_out, int out_size) {
    const float* x     = (const float*)d_in[0];
    const float* vm    = (const float*)d_in[1];
    const float* Ks    = (const float*)d_in[2];
    const float* wqkv  = (const float*)d_in[3];
    const float* wproj = (const float*)d_in[4];
    float* out = (float*)d_out;

    void *p_xs, *p_wqs, *p_wps, *p_ys;
    cudaGetSymbolAddress(&p_xs,  g_xs);
    cudaGetSymbolAddress(&p_wqs, g_wqs);
    cudaGetSymbolAddress(&p_wps, g_wps);
    cudaGetSymbolAddress(&p_ys,  g_ys);

    cudaFuncSetAttribute(attn_mma, cudaFuncAttributeMaxDynamicSharedMemorySize, ATTN_SMEM);
    cudaFuncSetAttribute(gemm_mma<0>, cudaFuncAttributeMaxDynamicSharedMemorySize, GSM_TOTAL);
    cudaFuncSetAttribute(gemm_mma<1>, cudaFuncAttributeMaxDynamicSharedMemorySize, GSM_TOTAL);

    cam_kernel<<<1, 32>>>(vm, Ks);
    m_kernel<<<256, 256>>>();
    split3_kernel<<<1024, 256>>>(x, wqkv, wproj);
    gemm_mma<0><<<dim3(24, 32), 256, GSM_TOTAL>>>((const __nv_bfloat16*)p_xs,
                                                  (const __nv_bfloat16*)p_wqs, nullptr);
    attn_mma<<<dim3(16, 32), 256, ATTN_SMEM>>>();
    gemm_mma<1><<<dim3(8, 32), 256, GSM_TOTAL>>>((const __nv_bfloat16*)p_ys,
                                                 (const __nv_bfloat16*)p_wps, out);
}

// round 12
// speedup vs baseline: 1.0006x; 1.0006x over previous
#include <cuda_runtime.h>
#include <cuda_bf16.h>
#include <math.h>
#include <stdint.h>

// Problem constants
#define NB    2
#define NL    2048
#define NH    16
#define ND    64
#define NDIM  1024
#define NC    8
#define NPC   256
#define NG    16
#define NBC   (NB*NC)

// Scratch (device globals; no allocation allowed)
__device__ float g_Mq [NBC*NPC*NG*16];
__device__ float g_Mkv[NBC*NPC*NG*16];
__device__ float g_Mo [NBC*NPC*NG*16];
__device__ float g_P  [NBC*16];
__device__ float g_Pi [NBC*16];

// bf16 hi/lo split buffers (GEMM operands): per 32-float chunk -> [32 hi | 32 lo]
__device__ __align__(128) __nv_bfloat16 g_xs [4096*2048];   // x split
__device__ __align__(128) __nv_bfloat16 g_wqs[3072*2048];   // w_qkv split
__device__ __align__(128) __nv_bfloat16 g_wps[1024*2048];   // w_proj split
__device__ __align__(128) __nv_bfloat16 g_ys [4096*2048];   // attention out split

// attention operands: [bh][token][hi d0..63 | lo d0..63] bf16 (256B rows)
__device__ __align__(128) __nv_bfloat16 g_qs [32*2048*128];
__device__ __align__(128) __nv_bfloat16 g_ks [32*2048*128];
__device__ __align__(128) __nv_bfloat16 g_vs [32*2048*128];

// ---------------------------------------------------------------------------
// PTX helpers (sm_103-safe: mma.sync / ldmatrix / cp.async only)
// ---------------------------------------------------------------------------
__device__ __forceinline__ uint32_t smem_u32(const void* p) {
    uint32_t a;
    asm("{ .reg .u64 t; cvta.to.shared.u64 t, %1; cvt.u32.u64 %0, t; }" : "=r"(a) : "l"(p));
    return a;
}
__device__ __forceinline__ void cpa16(uint32_t sdst, const void* gsrc) {
    asm volatile("cp.async.cg.shared.global [%0], [%1], 16;" :: "r"(sdst), "l"(gsrc) : "memory");
}
#define CP_COMMIT() asm volatile("cp.async.commit_group;" ::: "memory")
#define CP_WAIT(n)  asm volatile("cp.async.wait_group %0;" :: "n"(n) : "memory")

__device__ __forceinline__ void ldsm_x4(uint32_t addr, uint32_t* r) {
    asm volatile("ldmatrix.sync.aligned.m8n8.x4.shared.b16 {%0,%1,%2,%3}, [%4];"
        : "=r"(r[0]), "=r"(r[1]), "=r"(r[2]), "=r"(r[3]) : "r"(addr));
}
__device__ __forceinline__ void ldsm_x4_t(uint32_t addr, uint32_t* r) {
    asm volatile("ldmatrix.sync.aligned.m8n8.x4.trans.shared.b16 {%0,%1,%2,%3}, [%4];"
        : "=r"(r[0]), "=r"(r[1]), "=r"(r[2]), "=r"(r[3]) : "r"(addr));
}
__device__ __forceinline__ void mma16816(float* c, const uint32_t* a, uint32_t b0, uint32_t b1) {
    asm volatile("mma.sync.aligned.m16n8k16.row.col.f32.bf16.bf16.f32 "
        "{%0,%1,%2,%3}, {%4,%5,%6,%7}, {%8,%9}, {%0,%1,%2,%3};"
        : "+f"(c[0]), "+f"(c[1]), "+f"(c[2]), "+f"(c[3])
        : "r"(a[0]), "r"(a[1]), "r"(a[2]), "r"(a[3]), "r"(b0), "r"(b1));
}
// swizzled smem address: 256B-pitch rows, 16B segs, seg ^= row&7
__device__ __forceinline__ uint32_t asw(uint32_t base, int row, int seg) {
    return base + row * 256 + ((seg ^ (row & 7)) << 4);
}
// 128B-pitch version
__device__ __forceinline__ uint32_t sw_addr(uint32_t base, int row, int seg) {
    return base + row * 128 + ((seg ^ (row & 7)) << 4);
}

// ---------------------------------------------------------------------------
// Kernel 1: per-camera P = K4 @ viewmat and analytic P^{-1}
// ---------------------------------------------------------------------------
__global__ void cam_kernel(const float* __restrict__ vm, const float* __restrict__ Kin) {
    int t = threadIdx.x;
    if (t >= NBC) return;
    const float* V = vm + t * 16;
    const float* K = Kin + t * 9;
    float P[16];
#pragma unroll
    for (int i = 0; i < 3; i++)
#pragma unroll
        for (int j = 0; j < 4; j++)
            P[i*4+j] = K[i*3+0]*V[0+j] + K[i*3+1]*V[4+j] + K[i*3+2]*V[8+j];
    P[12] = V[12]; P[13] = V[13]; P[14] = V[14]; P[15] = V[15];

    float Vi[16];
#pragma unroll
    for (int i = 0; i < 3; i++) {
#pragma unroll
        for (int j = 0; j < 3; j++) Vi[i*4+j] = V[j*4+i];
        Vi[i*4+3] = -(V[0*4+i]*V[3] + V[1*4+i]*V[7] + V[2*4+i]*V[11]);
    }
    Vi[12] = 0.f; Vi[13] = 0.f; Vi[14] = 0.f; Vi[15] = 1.f;

    float f = K[0], cx = K[2], cy = K[5];
    float invf = 1.0f / f;
    float Pi[16];
#pragma unroll
    for (int i = 0; i < 4; i++) {
        float c0 = Vi[i*4+0] * invf;
        float c1 = Vi[i*4+1] * invf;
        Pi[i*4+0] = c0;
        Pi[i*4+1] = c1;
        Pi[i*4+2] = Vi[i*4+2] - cx*c0 - cy*c1;
        Pi[i*4+3] = Vi[i*4+3];
    }
#pragma unroll
    for (int i = 0; i < 16; i++) { g_P[t*16+i] = P[i]; g_Pi[t*16+i] = Pi[i]; }
}

// ---------------------------------------------------------------------------
// Kernel 2: per-(b,c,p,g) transforms Mq, Mkv, Mo
// ---------------------------------------------------------------------------
__global__ void m_kernel() {
    int i = blockIdx.x * blockDim.x + threadIdx.x;
    int g  = i & 15;
    int p  = (i >> 4) & 255;
    int bc = i >> 12;
    const float* P  = g_P  + bc * 16;
    const float* Pi = g_Pi + bc * 16;

    float u = ((p & 15) + 0.5f) * 16.0f;
    float v = ((p >> 4) + 0.5f) * 16.0f;
    float fr = powf(10000.0f, -(float)g / 16.0f);
    float sa, ca, sb, cb;
    sincosf(u * fr, &sa, &ca);
    sincosf(v * fr, &sb, &cb);

    float* mq  = g_Mq  + i * 16;
    float* mkv = g_Mkv + i * 16;
    float* mo  = g_Mo  + i * 16;
#pragma unroll
    for (int r = 0; r < 4; r++) {
        float p0 = Pi[0*4+r], p1 = Pi[1*4+r], p2 = Pi[2*4+r], p3 = Pi[3*4+r];
        mq[r*4+0] =  p0*ca + p1*sa;
        mq[r*4+1] = -p0*sa + p1*ca;
        mq[r*4+2] =  p2*cb + p3*sb;
        mq[r*4+3] = -p2*sb + p3*cb;
        float q0 = P[r*4+0], q1 = P[r*4+1], q2 = P[r*4+2], q3 = P[r*4+3];
        mkv[r*4+0] =  q0*ca + q1*sa;
        mkv[r*4+1] = -q0*sa + q1*ca;
        mkv[r*4+2] =  q2*cb + q3*sb;
        mkv[r*4+3] = -q2*sb + q3*cb;
    }
#pragma unroll
    for (int k = 0; k < 4; k++) {
        float p0 = Pi[0*4+k], p1 = Pi[4+k], p2 = Pi[8+k], p3 = Pi[12+k];
        mo[0*4+k] =  ca*p0 + sa*p1;
        mo[1*4+k] = -sa*p0 + ca*p1;
        mo[2*4+k] =  cb*p2 + sb*p3;
        mo[3*4+k] = -sb*p2 + cb*p3;
    }
}

// ---------------------------------------------------------------------------
// bf16 hi/lo split for all three GEMM inputs, one launch.
// ---------------------------------------------------------------------------
__global__ void __launch_bounds__(256) split3_kernel(const float* __restrict__ x,
                                                     const float* __restrict__ wq,
                                                     const float* __restrict__ wp) {
    int c = blockIdx.x * 256 + threadIdx.x;
    const float* src; __nv_bfloat16* dst; int cc;
    if (c < 131072)      { src = x;  dst = g_xs;  cc = c; }
    else if (c < 229376) { src = wq; dst = g_wqs; cc = c - 131072; }
    else                 { src = wp; dst = g_wps; cc = c - 229376; }
    const float4* s = (const float4*)src + (size_t)cc * 8;
    __nv_bfloat162 H[16], L[16];
#pragma unroll
    for (int i = 0; i < 8; i++) {
        float4 f = s[i];
        float vv[4] = {f.x, f.y, f.z, f.w};
#pragma unroll
        for (int j = 0; j < 2; j++) {
            float a = vv[2*j], b = vv[2*j+1];
            __nv_bfloat16 ha = __float2bfloat16_rn(a);
            __nv_bfloat16 hb = __float2bfloat16_rn(b);
            __nv_bfloat16 la = __float2bfloat16_rn(a - __bfloat162float(ha));
            __nv_bfloat16 lb = __float2bfloat16_rn(b - __bfloat162float(hb));
            H[i*2+j] = __halves2bfloat162(ha, hb);
            L[i*2+j] = __halves2bfloat162(la, lb);
        }
    }
    uint4* d = (uint4*)(dst + (size_t)cc * 64);
    const uint4* hv = (const uint4*)H;
    const uint4* lv = (const uint4*)L;
#pragma unroll
    for (int i = 0; i < 4; i++) d[i] = hv[i];
#pragma unroll
    for (int i = 0; i < 4; i++) d[4+i] = lv[i];
}

// ---------------------------------------------------------------------------
// mma.sync split-bf16 GEMM, GS=3, 2 CTAs/SM, ONE sync per stage, load-first.
// MODE 0: qkv — fused Mq/Mkv transform epilogue -> split bf16 g_qs/g_ks/g_vs
// MODE 1: proj — plain fp32 epilogue to Cout
// ---------------------------------------------------------------------------
#define GS        3
#define GSTAGE_B  32768
#define GSM_TOTAL (GS*GSTAGE_B)   // 98304

__device__ __forceinline__ void g_load_stage(uint32_t sA, uint32_t sB,
        const char* Ab, const char* Bb, int m0, int n0, int kc, int tid) {
#pragma unroll
    for (int it = 0; it < 4; it++) {
        int u = tid + it * 256;
        int r = u >> 3, s = u & 7;
        cpa16(sw_addr(sA, r, s), Ab + ((size_t)(m0 + r) * 32 + kc) * 128 + s * 16);
    }
#pragma unroll
    for (int it = 0; it < 4; it++) {
        int u = tid + it * 256;
        int r = u >> 3, s = u & 7;
        cpa16(sw_addr(sB, r, s), Bb + ((size_t)(n0 + r) * 32 + kc) * 128 + s * 16);
    }
}

template <int MODE>
__global__ void __launch_bounds__(256, 2) gemm_mma(const __nv_bfloat16* __restrict__ Abf,
                                                   const __nv_bfloat16* __restrict__ Bbf,
                                                   float* __restrict__ Cout) {
    extern __shared__ char smem[];
    uint32_t sb = smem_u32(smem);
    int tid = threadIdx.x, wid = tid >> 5, lane = tid & 31;
    int m0 = blockIdx.y * 128, n0 = blockIdx.x * 128;
    const char* Ab = (const char*)Abf;
    const char* Bb = (const char*)Bbf;

    int wm = (wid & 3) * 32;
    int wn = (wid >> 2) * 64;
    int lrow = lane & 7;
    int lm8  = (lane >> 3) & 1;
    int lk   = lane >> 4;

    float acc[2][8][4];
#pragma unroll
    for (int t = 0; t < 2; t++)
#pragma unroll
        for (int g = 0; g < 8; g++)
#pragma unroll
            for (int r = 0; r < 4; r++) acc[t][g][r] = 0.f;

    // prologue: prefetch chunks 0..GS-2
#pragma unroll
    for (int s = 0; s < GS - 1; s++) {
        uint32_t sA = sb + s * GSTAGE_B;
        g_load_stage(sA, sA + 16384, Ab, Bb, m0, n0, s, tid);
        CP_COMMIT();
    }

    const int stepA[6] = {0, 2, 0, 2, 4, 6};
    const int stepB[6] = {0, 2, 4, 6, 0, 2};

    int sload = GS - 1;   // slot receiving chunk i+GS-1
    int scomp = 0;        // slot holding chunk i
    for (int i = 0; i < 32; i++) {
        CP_WAIT(GS - 2);        // FIFO retirement => chunk i resident
        __syncthreads();        // all warps done reading slot sload (iter i-1)
        if (i + GS - 1 < 32) {
            uint32_t dA = sb + sload * GSTAGE_B;
            g_load_stage(dA, dA + 16384, Ab, Bb, m0, n0, i + GS - 1, tid);
        }
        CP_COMMIT();
        uint32_t sA = sb + scomp * GSTAGE_B;
        uint32_t sB = sA + 16384;
#pragma unroll
        for (int st = 0; st < 6; st++) {
            int sa0 = stepA[st], sb0 = stepB[st];
            uint32_t a[2][4];
#pragma unroll
            for (int t = 0; t < 2; t++) {
                int row = wm + t * 16 + lm8 * 8 + lrow;
                ldsm_x4(sw_addr(sA, row, sa0 + lk), a[t]);
            }
            uint32_t b[4][4];
#pragma unroll
            for (int g = 0; g < 4; g++) {
                int row = wn + g * 16 + lm8 * 8 + lrow;
                ldsm_x4(sw_addr(sB, row, sb0 + lk), b[g]);
            }
#pragma unroll
            for (int t = 0; t < 2; t++)
#pragma unroll
                for (int g = 0; g < 4; g++) {
                    mma16816(acc[t][2*g],   a[t], b[g][0], b[g][2]);
                    mma16816(acc[t][2*g+1], a[t], b[g][1], b[g][3]);
                }
        }
        sload = (sload + 1 == GS) ? 0 : sload + 1;
        scomp = (scomp + 1 == GS) ? 0 : scomp + 1;
    }

    int mrow = (lane >> 2);
    int ncol = (lane & 3) * 2;

    if (MODE == 1) {
#pragma unroll
        for (int t = 0; t < 2; t++)
#pragma unroll
            for (int g = 0; g < 8; g++) {
                int n = n0 + wn + (g >> 1) * 16 + (g & 1) * 8 + ncol;
                int m = m0 + wm + t * 16 + mrow;
#pragma unroll
                for (int half = 0; half < 2; half++) {
                    int mm = m + half * 8;
                    *(float2*)(Cout + (size_t)mm * NDIM + n) =
                        make_float2(acc[t][g][half*2], acc[t][g][half*2+1]);
                }
            }
        return;
    }

    // MODE 0: fused transform epilogue. Stage fp32 tile in smem (pitch 132).
    CP_WAIT(0);
    __syncthreads();
    float* os = (float*)smem;
#pragma unroll
    for (int t = 0; t < 2; t++)
#pragma unroll
        for (int g = 0; g < 8; g++) {
            int nn = wn + (g >> 1) * 16 + (g & 1) * 8 + ncol;
#pragma unroll
            for (int half = 0; half < 2; half++) {
                int mmr = wm + t * 16 + mrow + half * 8;
                *(float2*)&os[mmr * 132 + nn] =
                    make_float2(acc[t][g][half*2], acc[t][g][half*2+1]);
            }
        }
    __syncthreads();

    int tt = n0 >> 10;   // 0=q, 1=k, 2=v
    const float* Mbase = (tt == 0) ? g_Mq : g_Mkv;
    __nv_bfloat16* obase = (tt == 0) ? g_qs : (tt == 1) ? g_ks : g_vs;
    float qscale = (tt == 0) ? 0.125f : 1.0f;
#pragma unroll
    for (int it2 = 0; it2 < 16; it2++) {
        int idx = tid + it2 * 256;
        int row = idx >> 5, gi = idx & 31;
        int m = m0 + row;
        int b = m >> 11, l = m & 2047;
        int n = n0 + gi * 4;
        int h = (n >> 6) & 15, g = (n & 63) >> 2;
        int c = l >> 8, p = l & 255;
        const float* M = Mbase + ((size_t)(((b << 3) + c) * NPC + p) * NG + g) * 16;
        float4 tv = *(float4*)&os[row * 132 + gi * 4];
        float y0 = (M[0]*tv.x  + M[1]*tv.y  + M[2]*tv.z  + M[3]*tv.w)  * qscale;
        float y1 = (M[4]*tv.x  + M[5]*tv.y  + M[6]*tv.z  + M[7]*tv.w)  * qscale;
        float y2 = (M[8]*tv.x  + M[9]*tv.y  + M[10]*tv.z + M[11]*tv.w) * qscale;
        float y3 = (M[12]*tv.x + M[13]*tv.y + M[14]*tv.z + M[15]*tv.w) * qscale;
        __nv_bfloat16 hi[4], lo[4];
        float vv[4] = {y0, y1, y2, y3};
#pragma unroll
        for (int j = 0; j < 4; j++) {
            hi[j] = __float2bfloat16_rn(vv[j]);
            lo[j] = __float2bfloat16_rn(vv[j] - __bfloat162float(hi[j]));
        }
        size_t tb = ((size_t)((b << 4) + h) * NL + l) * 128;
        *(uint2*)(obase + tb + g * 4)      = *(uint2*)hi;
        *(uint2*)(obase + tb + 64 + g * 4) = *(uint2*)lo;
    }
}

// ---------------------------------------------------------------------------
// Kernel 5: flash attention with split-bf16 mma.sync, 2 CTAs/SM (unchanged).
// ---------------------------------------------------------------------------
#define ATTN_SMEM 98304

__device__ __forceinline__ void attn_load_kv(uint32_t Kb, uint32_t Vb,
        const char* Ksrc, const char* Vsrc, int tid) {
#pragma unroll
    for (int it2 = 0; it2 < 4; it2++) {
        int u = tid + it2 * 256;
        int r = u >> 4, s = u & 15;
        cpa16(asw(Kb, r, s), Ksrc + (size_t)r * 256 + s * 16);
    }
#pragma unroll
    for (int it2 = 0; it2 < 4; it2++) {
        int u = tid + it2 * 256;
        int r = u >> 4, s = u & 15;
        cpa16(asw(Vb, r, s), Vsrc + (size_t)r * 256 + s * 16);
    }
}

__global__ void __launch_bounds__(256, 2) attn_mma() {
    extern __shared__ char smem[];
    uint32_t sb = smem_u32(smem);
    uint32_t Qs = sb;                       // 128 rows x 256B
    int bh = blockIdx.y;
    int b = bh >> 4, h = bh & 15;
    int q0 = blockIdx.x * 128;
    int tid = threadIdx.x, wid = tid >> 5, lane = tid & 31;

    const char* Qg = (const char*)g_qs + ((size_t)bh * NL + q0) * 256;
    const char* Kg = (const char*)g_ks + (size_t)bh * NL * 256;
    const char* Vg = (const char*)g_vs + (size_t)bh * NL * 256;

#pragma unroll
    for (int it2 = 0; it2 < 8; it2++) {
        int u = tid + it2 * 256;
        int r = u >> 4, s = u & 15;
        cpa16(asw(Qs, r, s), Qg + (size_t)r * 256 + s * 16);
    }
    attn_load_kv(sb + 32768, sb + 32768 + 16384, Kg, Vg, tid);
    CP_COMMIT();
    CP_WAIT(0);
    __syncthreads();

    int wq = wid * 16;
    int lrow8 = (lane & 7) + ((lane >> 3) & 1) * 8;
    int lseg  = lane >> 4;
    uint32_t qh[4][4];
#pragma unroll
    for (int kc = 0; kc < 4; kc++)
        ldsm_x4(asw(Qs, wq + lrow8, kc*2 + lseg), qh[kc]);

    float oacc[8][4];
#pragma unroll
    for (int n = 0; n < 8; n++)
#pragma unroll
        for (int r = 0; r < 4; r++) oacc[n][r] = 0.f;
    float mi0 = -1e30f, mi1 = -1e30f, li0 = 0.f, li1 = 0.f;

    for (int it = 0; it < 32; it++) {
        if (it + 1 < 32)
            attn_load_kv(sb + 32768 + ((it+1)&1)*32768, sb + 32768 + ((it+1)&1)*32768 + 16384,
                         Kg + (size_t)(it+1)*64*256, Vg + (size_t)(it+1)*64*256, tid);
        CP_COMMIT();
        uint32_t Kb = sb + 32768 + (it&1)*32768;
        uint32_t Vb = Kb + 16384;

        // S = Q K^T (3-term split; Q-lo frag reloaded from smem)
        float sacc[8][4];
#pragma unroll
        for (int n = 0; n < 8; n++)
#pragma unroll
            for (int r = 0; r < 4; r++) sacc[n][r] = 0.f;
#pragma unroll
        for (int kc = 0; kc < 4; kc++) {
            uint32_t ql[4];
            ldsm_x4(asw(Qs, wq + lrow8, 8 + kc*2 + lseg), ql);
#pragma unroll
            for (int np = 0; np < 4; np++) {
                uint32_t kh[4], kl[4];
                int krow = np*16 + lrow8;
                ldsm_x4(asw(Kb, krow, kc*2 + lseg), kh);
                ldsm_x4(asw(Kb, krow, 8 + kc*2 + lseg), kl);
                mma16816(sacc[2*np],   qh[kc], kh[0], kh[2]);
                mma16816(sacc[2*np+1], qh[kc], kh[1], kh[3]);
                mma16816(sacc[2*np],   qh[kc], kl[0], kl[2]);
                mma16816(sacc[2*np+1], qh[kc], kl[1], kl[3]);
                mma16816(sacc[2*np],   ql, kh[0], kh[2]);
                mma16816(sacc[2*np+1], ql, kh[1], kh[3]);
            }
        }

        // online softmax (rows r = lane>>2 and r+8)
        float m0 = -1e30f, m1 = -1e30f;
#pragma unroll
        for (int n = 0; n < 8; n++) {
            m0 = fmaxf(m0, fmaxf(sacc[n][0], sacc[n][1]));
            m1 = fmaxf(m1, fmaxf(sacc[n][2], sacc[n][3]));
        }
        m0 = fmaxf(m0, __shfl_xor_sync(0xffffffffu, m0, 1));
        m0 = fmaxf(m0, __shfl_xor_sync(0xffffffffu, m0, 2));
        m1 = fmaxf(m1, __shfl_xor_sync(0xffffffffu, m1, 1));
        m1 = fmaxf(m1, __shfl_xor_sync(0xffffffffu, m1, 2));
        float nm0 = fmaxf(mi0, m0), nm1 = fmaxf(mi1, m1);
        float al0 = __expf(mi0 - nm0), al1 = __expf(mi1 - nm1);
        mi0 = nm0; mi1 = nm1;

        float rs0 = 0.f, rs1 = 0.f;
#pragma unroll
        for (int n = 0; n < 8; n++) {
            sacc[n][0] = __expf(sacc[n][0] - nm0);
            sacc[n][1] = __expf(sacc[n][1] - nm0);
            sacc[n][2] = __expf(sacc[n][2] - nm1);
            sacc[n][3] = __expf(sacc[n][3] - nm1);
            rs0 += sacc[n][0] + sacc[n][1];
            rs1 += sacc[n][2] + sacc[n][3];
        }
        rs0 += __shfl_xor_sync(0xffffffffu, rs0, 1);
        rs0 += __shfl_xor_sync(0xffffffffu, rs0, 2);
        rs1 += __shfl_xor_sync(0xffffffffu, rs1, 1);
        rs1 += __shfl_xor_sync(0xffffffffu, rs1, 2);
        li0 = li0 * al0 + rs0;
        li1 = li1 * al1 + rs1;
#pragma unroll
        for (int n = 0; n < 8; n++) {
            oacc[n][0] *= al0; oacc[n][1] *= al0;
            oacc[n][2] *= al1; oacc[n][3] *= al1;
        }

        // O += P V (3-term split); P converted per-kc from sacc
#pragma unroll
        for (int kc = 0; kc < 4; kc++) {
            uint32_t af[4], amf[4];
#pragma unroll
            for (int half = 0; half < 2; half++) {
                const float* s0 = sacc[2*kc + half];
                __nv_bfloat162 h01 = __floats2bfloat162_rn(s0[0], s0[1]);
                __nv_bfloat162 h23 = __floats2bfloat162_rn(s0[2], s0[3]);
                float2 f01 = __bfloat1622float2(h01);
                float2 f23 = __bfloat1622float2(h23);
                __nv_bfloat162 l01 = __floats2bfloat162_rn(s0[0] - f01.x, s0[1] - f01.y);
                __nv_bfloat162 l23 = __floats2bfloat162_rn(s0[2] - f23.x, s0[3] - f23.y);
                af[half*2]   = *(uint32_t*)&h01;
                af[half*2+1] = *(uint32_t*)&h23;
                amf[half*2]   = *(uint32_t*)&l01;
                amf[half*2+1] = *(uint32_t*)&l23;
            }
#pragma unroll
            for (int dp = 0; dp < 4; dp++) {
                uint32_t vh[4], vl[4];
                int vrow = kc*16 + lrow8;
                ldsm_x4_t(asw(Vb, vrow, dp*2 + lseg), vh);
                ldsm_x4_t(asw(Vb, vrow, 8 + dp*2 + lseg), vl);
                mma16816(oacc[2*dp],   af, vh[0], vh[1]);
                mma16816(oacc[2*dp+1], af, vh[2], vh[3]);
                mma16816(oacc[2*dp],   af, vl[0], vl[1]);
                mma16816(oacc[2*dp+1], af, vl[2], vl[3]);
                mma16816(oacc[2*dp],   amf, vh[0], vh[1]);
                mma16816(oacc[2*dp+1], amf, vh[2], vh[3]);
            }
        }
        if (it + 1 < 32) { CP_WAIT(0); __syncthreads(); }
    }

    // epilogue: normalized o -> smem, then Mo + split-store to g_ys
    __syncthreads();
    float* os = (float*)(smem + 32768);   // [128][65] f32
    float inv0 = 1.0f / li0, inv1 = 1.0f / li1;
    int r = wq + (lane >> 2);
    int cb = (lane & 3) * 2;
#pragma unroll
    for (int n = 0; n < 8; n++) {
        os[r*65 + n*8 + cb]         = oacc[n][0] * inv0;
        os[r*65 + n*8 + cb + 1]     = oacc[n][1] * inv0;
        os[(r+8)*65 + n*8 + cb]     = oacc[n][2] * inv1;
        os[(r+8)*65 + n*8 + cb + 1] = oacc[n][3] * inv1;
    }
    __syncthreads();

#pragma unroll
    for (int it2 = 0; it2 < 8; it2++) {
        int u = tid + it2 * 256;
        int qq = u >> 4, g = u & 15;
        int l = q0 + qq;
        int c = l >> 8, p = l & 255;
        const float* Mo = g_Mo + ((size_t)(((b << 3) + c) * NPC + p) * NG + g) * 16;
        float o0 = os[qq*65 + g*4 + 0];
        float o1 = os[qq*65 + g*4 + 1];
        float o2 = os[qq*65 + g*4 + 2];
        float o3 = os[qq*65 + g*4 + 3];
        float y0 = Mo[0]*o0  + Mo[1]*o1  + Mo[2]*o2  + Mo[3]*o3;
        float y1 = Mo[4]*o0  + Mo[5]*o1  + Mo[6]*o2  + Mo[7]*o3;
        float y2 = Mo[8]*o0  + Mo[9]*o1  + Mo[10]*o2 + Mo[11]*o3;
        float y3 = Mo[12]*o0 + Mo[13]*o1 + Mo[14]*o2 + Mo[15]*o3;
        __nv_bfloat16 hi[4], lo[4];
        float vv[4] = {y0, y1, y2, y3};
#pragma unroll
        for (int j = 0; j < 4; j++) {
            hi[j] = __float2bfloat16_rn(vv[j]);
            lo[j] = __float2bfloat16_rn(vv[j] - __bfloat162float(hi[j]));
        }
        int m = b * NL + l;
        int col = h * 64 + g * 4;
        int chunk = col >> 5, cof = col & 31;
        __nv_bfloat16* dst = g_ys + ((size_t)m * 32 + chunk) * 64 + cof;
        *(uint2*)dst        = *(uint2*)hi;
        *(uint2*)(dst + 32) = *(uint2*)lo;
    }
}

// ---------------------------------------------------------------------------
extern "C" void kernel_launch(void* const* d_in, const int* in_sizes, int n_in,
                              void* d_out, int out_size) {
    const float* x     = (const float*)d_in[0];
    const float* vm    = (const float*)d_in[1];
    const float* Ks    = (const float*)d_in[2];
    const float* wqkv  = (const float*)d_in[3];
    const float* wproj = (const float*)d_in[4];
    float* out = (float*)d_out;

    void *p_xs, *p_wqs, *p_wps, *p_ys;
    cudaGetSymbolAddress(&p_xs,  g_xs);
    cudaGetSymbolAddress(&p_wqs, g_wqs);
    cudaGetSymbolAddress(&p_wps, g_wps);
    cudaGetSymbolAddress(&p_ys,  g_ys);

    cudaFuncSetAttribute(attn_mma, cudaFuncAttributeMaxDynamicSharedMemorySize, ATTN_SMEM);
    cudaFuncSetAttribute(gemm_mma<0>, cudaFuncAttributeMaxDynamicSharedMemorySize, GSM_TOTAL);
    cudaFuncSetAttribute(gemm_mma<1>, cudaFuncAttributeMaxDynamicSharedMemorySize, GSM_TOTAL);

    cam_kernel<<<1, 32>>>(vm, Ks);
    m_kernel<<<256, 256>>>();
    split3_kernel<<<1024, 256>>>(x, wqkv, wproj);
    gemm_mma<0><<<dim3(24, 32), 256, GSM_TOTAL>>>((const __nv_bfloat16*)p_xs,
                                                  (const __nv_bfloat16*)p_wqs, nullptr);
    attn_mma<<<dim3(16, 32), 256, ATTN_SMEM>>>();
    gemm_mma<1><<<dim3(8, 32), 256, GSM_TOTAL>>>((const __nv_bfloat16*)p_ys,
                                                 (const __nv_bfloat16*)p_wps, out);
}